// round 2
// baseline (speedup 1.0000x reference)
#include <cuda_runtime.h>
#include <math.h>

#define N0 32768
#define N1 8192
#define N2 2048
#define E0 (N0*8)
#define E1 (N1*8)
#define E2 (N2*8)
#define CC 32

// ---------------- static scratch (no allocation allowed) ----------------
__device__ __align__(16) float g_bufA[N0*3*CC];
__device__ __align__(16) float g_bufB[N0*3*CC];
__device__ __align__(16) float g_x0[N0*3*CC];
__device__ __align__(16) float g_x1[N1*3*CC];
__device__ __align__(16) float g_q[N0*3*CC];
__device__ __align__(16) float g_k[N0*3*CC];
__device__ __align__(16) float g_v[N0*3*CC];
__device__ __align__(16) float g_s[N0*3*CC];
__device__ __align__(16) float g_pos1[N1*3];
__device__ __align__(16) float g_pos2[N2*3];
__device__ int g_rowptr[(N0+1)+(N1+1)+(N2+1)];
__device__ int g_cursor[(N0+1)+(N1+1)+(N2+1)];
__device__ int g_csrc[E0+E1+E2];
__device__ __align__(16) float4 g_crelr[E0+E1+E2];
__device__ float g_cntf[N1];

// ---------------- packed f32x2 helpers ----------------
__device__ __forceinline__ unsigned long long pk2(float lo, float hi){
    unsigned long long r;
    asm("mov.b64 %0, {%1,%2};" : "=l"(r) : "f"(lo), "f"(hi));
    return r;
}
__device__ __forceinline__ unsigned long long ffma2(unsigned long long a, unsigned long long b, unsigned long long c){
    unsigned long long d;
    asm("fma.rn.f32x2 %0, %1, %2, %3;" : "=l"(d) : "l"(a), "l"(b), "l"(c));
    return d;
}
__device__ __forceinline__ float2 upk2(unsigned long long v){
    float2 r;
    asm("mov.b64 {%0,%1}, %2;" : "=f"(r.x), "=f"(r.y) : "l"(v));
    return r;
}

// ---------------- small utility kernels ----------------
__global__ void gather_pos_k(const float* __restrict__ pos, const int* __restrict__ idx,
                             float* __restrict__ out, int N){
    int i = blockIdx.x*blockDim.x + threadIdx.x;
    if (i >= N) return;
    int s = idx[i];
    out[3*i+0] = pos[3*s+0];
    out[3*i+1] = pos[3*s+1];
    out[3*i+2] = pos[3*s+2];
}

__global__ void hist_k(const int* __restrict__ dst, int* __restrict__ cnt, int E){
    int e = blockIdx.x*blockDim.x + threadIdx.x;
    if (e >= E) return;
    atomicAdd(&cnt[dst[e]], 1);
}

// single-block exclusive scan, n <= 32768
__global__ void scan_k(const int* __restrict__ cnt, int* __restrict__ rp, int n){
    __shared__ int sm[1024];
    int t = threadIdx.x;
    int chunk = (n + 1023) >> 10;
    int lo = t*chunk;
    int hi = min(n, lo+chunk);
    int loc[32];
    int s = 0;
    for (int i = lo; i < hi; i++){ int vv = cnt[i]; loc[i-lo] = vv; s += vv; }
    sm[t] = s;
    __syncthreads();
    for (int off = 1; off < 1024; off <<= 1){
        int vv = (t >= off) ? sm[t-off] : 0;
        __syncthreads();
        sm[t] += vv;
        __syncthreads();
    }
    int base = (t > 0) ? sm[t-1] : 0;
    for (int i = lo; i < hi; i++){ rp[i] = base; base += loc[i-lo]; }
    if (t == 0) rp[n] = sm[1023];
}

__global__ void build_csr_k(const int* __restrict__ src, const int* __restrict__ dst,
                            const float* __restrict__ pos,
                            int* __restrict__ cursor, int* __restrict__ csrc,
                            float4* __restrict__ crelr, int E){
    int e = blockIdx.x*blockDim.x + threadIdx.x;
    if (e >= E) return;
    int d = dst[e];
    int s = src[e];
    int slot = atomicAdd(&cursor[d], 1);
    float dx = pos[3*d+0] - pos[3*s+0];
    float dy = pos[3*d+1] - pos[3*s+1];
    float dz = pos[3*d+2] - pos[3*s+2];
    float r = sqrtf(dx*dx + dy*dy + dz*dz + 1e-12f);
    csrc[slot] = s;
    crelr[slot] = make_float4(dx, dy, dz, r);
}

// ---------------- q,k,v,skip projection ----------------
// x layout: [n][v][c]  (row t = n*3+v, contiguous CIN channels)
template<int CIN, int COUT>
__global__ void qkvs_k(const float* __restrict__ x,
                       const float* __restrict__ Wq, const float* __restrict__ Wk,
                       const float* __restrict__ Wv, const float* __restrict__ Ws,
                       float* __restrict__ q, float* __restrict__ k,
                       float* __restrict__ v, float* __restrict__ sk, int rows){
    __shared__ __align__(16) float sW[4][CIN*COUT];
    {
        const float* Wsrc[4] = {Wq, Wk, Wv, Ws};
        #pragma unroll
        for (int m2 = 0; m2 < 4; m2++)
            for (int i = threadIdx.x; i < CIN*COUT; i += blockDim.x)
                sW[m2][i] = Wsrc[m2][i];
    }
    __syncthreads();
    int t = blockIdx.x*blockDim.x + threadIdx.x;
    if (t >= rows) return;
    float xr[CIN];
    #pragma unroll
    for (int c = 0; c < CIN; c++) xr[c] = x[t*CIN + c];
    float* outs[4] = {q, k, v, sk};
    #pragma unroll
    for (int m2 = 0; m2 < 4; m2++){
        if (COUT == 1){
            float acc = 0.f;
            #pragma unroll
            for (int c = 0; c < CIN; c++) acc = fmaf(xr[c], sW[m2][c], acc);
            outs[m2][t] = acc;
        } else {
            unsigned long long acc[COUT/2 > 0 ? COUT/2 : 1];
            #pragma unroll
            for (int op = 0; op < COUT/2; op++) acc[op] = 0ULL;
            #pragma unroll
            for (int c = 0; c < CIN; c++){
                unsigned long long xx = pk2(xr[c], xr[c]);
                const unsigned long long* wp =
                    reinterpret_cast<const unsigned long long*>(&sW[m2][c*COUT]);
                #pragma unroll
                for (int op = 0; op < COUT/2; op++)
                    acc[op] = ffma2(wp[op], xx, acc[op]);
            }
            float2* outp = reinterpret_cast<float2*>(outs[m2] + t*COUT);
            #pragma unroll
            for (int op = 0; op < COUT/2; op++) outp[op] = upk2(acc[op]);
        }
    }
}

// ---------------- warp-per-node attention aggregation + norm_bias ----------------
template<int COUT>
__global__ void agg_k(const float* __restrict__ q, const float* __restrict__ k,
                      const float* __restrict__ v, const float* __restrict__ sk,
                      const int* __restrict__ rowptr, const int* __restrict__ csrc,
                      const float4* __restrict__ crelr,
                      const float* __restrict__ w1, const float* __restrict__ w2,
                      const float* __restrict__ scale, const float* __restrict__ bias,
                      float inv_scale, float* __restrict__ xout, int N){
    int gw = (blockIdx.x*blockDim.x + threadIdx.x) >> 5;
    int lane = threadIdx.x & 31;
    if (gw >= N) return;
    int n = gw;
    float q0 = 0.f, q1 = 0.f, q2 = 0.f;
    if (lane < COUT){
        const float* qp = q + n*3*COUT;
        q0 = qp[lane]; q1 = qp[COUT+lane]; q2 = qp[2*COUT+lane];
    }
    float w1v = 0.f, w2v = 0.f;
    if (lane < 16){ w1v = w1[lane]; w2v = w2[lane]; }
    int beg = rowptr[n], end = rowptr[n+1];
    float m = -INFINITY, ssum = 0.f, a0 = 0.f, a1 = 0.f, a2 = 0.f;
    for (int idx = beg; idx < end; idx++){
        int s = csrc[idx];
        float4 rr = crelr[idx];
        float kd = 0.f;
        if (lane < COUT){
            const float* kp = k + s*3*COUT;
            kd = q0*kp[lane] + q1*kp[COUT+lane] + q2*kp[2*COUT+lane];
        }
        float part = kd*inv_scale + ((lane < 16) ? fmaxf(rr.w*w1v, 0.f)*w2v : 0.f);
        #pragma unroll
        for (int off = 16; off; off >>= 1) part += __shfl_xor_sync(0xffffffffu, part, off);
        float logit = part;   // identical on all lanes
        float wgt;
        if (logit > m){
            float f = __expf(m - logit);
            ssum = ssum*f + 1.f;
            a0 *= f; a1 *= f; a2 *= f;
            m = logit; wgt = 1.f;
        } else {
            wgt = __expf(logit - m);
            ssum += wgt;
        }
        if (lane < COUT){
            const float* vp = v + s*3*COUT;
            a0 = fmaf(wgt, vp[lane]        + rr.x, a0);
            a1 = fmaf(wgt, vp[COUT+lane]   + rr.y, a1);
            a2 = fmaf(wgt, vp[2*COUT+lane] + rr.z, a2);
        }
    }
    if (lane < COUT){
        float inv = 1.f/(ssum + 1e-9f);   // matches ref: alpha = ex/(z+EPS) in max-shifted domain
        const float* sp = sk + n*3*COUT;
        float o0 = a0*inv + sp[lane];
        float o1 = a1*inv + sp[COUT+lane];
        float o2 = a2*inv + sp[2*COUT+lane];
        float nrm = sqrtf(o0*o0 + o1*o1 + o2*o2 + 1e-12f);
        float tt = fmaxf(scale[lane]*nrm + bias[lane], 0.f)/nrm;
        float* op = xout + n*3*COUT;
        op[lane]        = o0*tt;
        op[COUT+lane]   = o1*tt;
        op[2*COUT+lane] = o2*tt;
    }
}

// ---------------- pooling / upsample / head ----------------
__global__ void pool_scatter_k(const float* __restrict__ x, const int* __restrict__ cl,
                               float* __restrict__ out, int Nsrc){
    int i = blockIdx.x*blockDim.x + threadIdx.x;
    if (i >= Nsrc*96) return;
    int j = i/96, e = i%96;
    atomicAdd(&out[cl[j]*96 + e], x[i]);
}
__global__ void pool_cnt_k(const int* __restrict__ cl, float* __restrict__ cnt, int Nsrc){
    int i = blockIdx.x*blockDim.x + threadIdx.x;
    if (i >= Nsrc) return;
    atomicAdd(&cnt[cl[i]], 1.f);
}
__global__ void pool_div_k(float* __restrict__ out, const float* __restrict__ cnt, int Ndst){
    int i = blockIdx.x*blockDim.x + threadIdx.x;
    if (i >= Ndst*96) return;
    out[i] = out[i] / (cnt[i/96] + 1e-9f);
}
__global__ void scatter_add_k(float* __restrict__ out, const float* __restrict__ x,
                              const int* __restrict__ fp, int Nsrc){
    int i = blockIdx.x*blockDim.x + threadIdx.x;
    if (i >= Nsrc*96) return;
    int j = i/96, e = i%96;
    out[fp[j]*96 + e] += x[i];   // fp indices are unique -> race-free
}
__global__ void mlp_k(const float* __restrict__ x, const float* __restrict__ W,
                      float* __restrict__ y, int N){
    int t = blockIdx.x*blockDim.x + threadIdx.x;
    if (t >= N*40) return;
    int n = t/40, o = t%40;
    float a = x[3*n+0]*W[o] + x[3*n+1]*W[40+o] + x[3*n+2]*W[80+o];
    y[t] = fmaxf(a, 0.f);
}

// ---------------- host orchestration ----------------
struct Ptrs {
    float *bufA, *bufB, *x0s, *x1s, *q, *k, *v, *s, *pos1, *pos2, *cntf;
    int *rowptr, *cursor, *csrc;
    float4 *crelr;
};

static void run_layer(const Ptrs& P, const float* xin, float* xout, int lvl,
                      int cin, int cout,
                      const float* Wq, const float* Wk, const float* Wv, const float* Ws,
                      const float* sc, const float* bi,
                      const float* w1, const float* w2){
    int n   = (lvl == 0) ? N0 : (lvl == 1) ? N1 : N2;
    int rpo = (lvl == 0) ? 0  : (lvl == 1) ? (N0+1) : (N0+1+N1+1);
    int eo  = (lvl == 0) ? 0  : (lvl == 1) ? E0 : (E0+E1);
    int rows = n*3;
    if (cin == 1)
        qkvs_k<1,32><<<(rows+127)/128, 128>>>(xin, Wq, Wk, Wv, Ws, P.q, P.k, P.v, P.s, rows);
    else if (cout == 32)
        qkvs_k<32,32><<<(rows+127)/128, 128>>>(xin, Wq, Wk, Wv, Ws, P.q, P.k, P.v, P.s, rows);
    else
        qkvs_k<32,1><<<(rows+127)/128, 128>>>(xin, Wq, Wk, Wv, Ws, P.q, P.k, P.v, P.s, rows);
    float invs = 1.f/sqrtf(3.f*(float)cout);
    if (cout == 32)
        agg_k<32><<<n/8, 256>>>(P.q, P.k, P.v, P.s, P.rowptr+rpo, P.csrc+eo, P.crelr+eo,
                                w1, w2, sc, bi, invs, xout, n);
    else
        agg_k<1><<<n/8, 256>>>(P.q, P.k, P.v, P.s, P.rowptr+rpo, P.csrc+eo, P.crelr+eo,
                               w1, w2, sc, bi, invs, xout, n);
}

extern "C" void kernel_launch(void* const* d_in, const int* in_sizes, int n_in,
                              void* d_out, int out_size){
    const float* pos0   = (const float*)d_in[0];
    const float* v0     = (const float*)d_in[1];
    const float* WqF    = (const float*)d_in[2];
    const float* WkF    = (const float*)d_in[3];
    const float* WvF    = (const float*)d_in[4];
    const float* WsF    = (const float*)d_in[5];
    const float* WqM    = (const float*)d_in[6];
    const float* WkM    = (const float*)d_in[7];
    const float* WvM    = (const float*)d_in[8];
    const float* WsM    = (const float*)d_in[9];
    const float* WqL    = (const float*)d_in[10];
    const float* WkL    = (const float*)d_in[11];
    const float* WvL    = (const float*)d_in[12];
    const float* WsL    = (const float*)d_in[13];
    const float* wr1    = (const float*)d_in[14];
    const float* wr2    = (const float*)d_in[15];
    const float* sc_mid = (const float*)d_in[16];
    const float* bi_mid = (const float*)d_in[17];
    const float* sc_las = (const float*)d_in[18];
    const float* bi_las = (const float*)d_in[19];
    const float* Wmlp   = (const float*)d_in[20];
    const int* src0 = (const int*)d_in[21];
    const int* dst0 = (const int*)d_in[22];
    const int* src1 = (const int*)d_in[23];
    const int* dst1 = (const int*)d_in[24];
    const int* src2 = (const int*)d_in[25];
    const int* dst2 = (const int*)d_in[26];
    const int* fp1  = (const int*)d_in[27];
    const int* fp2  = (const int*)d_in[28];
    const int* cl1  = (const int*)d_in[29];
    const int* cl2  = (const int*)d_in[30];
    float* out = (float*)d_out;

    Ptrs P;
    cudaGetSymbolAddress((void**)&P.bufA, g_bufA);
    cudaGetSymbolAddress((void**)&P.bufB, g_bufB);
    cudaGetSymbolAddress((void**)&P.x0s,  g_x0);
    cudaGetSymbolAddress((void**)&P.x1s,  g_x1);
    cudaGetSymbolAddress((void**)&P.q,    g_q);
    cudaGetSymbolAddress((void**)&P.k,    g_k);
    cudaGetSymbolAddress((void**)&P.v,    g_v);
    cudaGetSymbolAddress((void**)&P.s,    g_s);
    cudaGetSymbolAddress((void**)&P.pos1, g_pos1);
    cudaGetSymbolAddress((void**)&P.pos2, g_pos2);
    cudaGetSymbolAddress((void**)&P.cntf, g_cntf);
    cudaGetSymbolAddress((void**)&P.rowptr, g_rowptr);
    cudaGetSymbolAddress((void**)&P.cursor, g_cursor);
    cudaGetSymbolAddress((void**)&P.csrc,   g_csrc);
    cudaGetSymbolAddress((void**)&P.crelr,  g_crelr);

    // geometry for levels 1 and 2
    gather_pos_k<<<(N1+255)/256, 256>>>(pos0, fp1, P.pos1, N1);
    gather_pos_k<<<(N2+255)/256, 256>>>(P.pos1, fp2, P.pos2, N2);

    // CSR per level (counting sort by dst), rel/r precomputed into csr order
    struct Lv { const int* src; const int* dst; const float* pos; int n; int e; int rpo; int eo; };
    Lv lv[3] = {
        {src0, dst0, pos0,   N0, E0, 0,            0},
        {src1, dst1, P.pos1, N1, E1, N0+1,         E0},
        {src2, dst2, P.pos2, N2, E2, N0+1+N1+1,    E0+E1}
    };
    for (int L = 0; L < 3; L++){
        cudaMemsetAsync(P.cursor + lv[L].rpo, 0, lv[L].n*sizeof(int), 0);
        hist_k<<<(lv[L].e+255)/256, 256>>>(lv[L].dst, P.cursor + lv[L].rpo, lv[L].e);
        scan_k<<<1, 1024>>>(P.cursor + lv[L].rpo, P.rowptr + lv[L].rpo, lv[L].n);
        cudaMemcpyAsync(P.cursor + lv[L].rpo, P.rowptr + lv[L].rpo,
                        lv[L].n*sizeof(int), cudaMemcpyDeviceToDevice, 0);
        build_csr_k<<<(lv[L].e+255)/256, 256>>>(lv[L].src, lv[L].dst, lv[L].pos,
                                                P.cursor + lv[L].rpo,
                                                P.csrc + lv[L].eo, P.crelr + lv[L].eo,
                                                lv[L].e);
    }

    const int MW = 1024; // 32*32 mid-weight stride

    // down block 0 (level 0)
    run_layer(P, v0,     P.bufA, 0, 1, 32, WqF, WkF, WvF, WsF,
              sc_mid+0,  bi_mid+0,  wr1+0,  wr2+0);
    run_layer(P, P.bufA, P.x0s,  0, 32, 32, WqM+0*MW, WkM+0*MW, WvM+0*MW, WsM+0*MW,
              sc_mid+32, bi_mid+32, wr1+16, wr2+16);

    // pool -> level 1
    cudaMemsetAsync(P.bufA, 0, N1*96*sizeof(float), 0);
    cudaMemsetAsync(P.cntf, 0, N1*sizeof(float), 0);
    pool_scatter_k<<<(N0*96+255)/256, 256>>>(P.x0s, cl1, P.bufA, N0);
    pool_cnt_k<<<(N0+255)/256, 256>>>(cl1, P.cntf, N0);
    pool_div_k<<<(N1*96+255)/256, 256>>>(P.bufA, P.cntf, N1);

    run_layer(P, P.bufA, P.bufB, 1, 32, 32, WqM+1*MW, WkM+1*MW, WvM+1*MW, WsM+1*MW,
              sc_mid+2*32, bi_mid+2*32, wr1+2*16, wr2+2*16);
    run_layer(P, P.bufB, P.x1s,  1, 32, 32, WqM+2*MW, WkM+2*MW, WvM+2*MW, WsM+2*MW,
              sc_mid+3*32, bi_mid+3*32, wr1+3*16, wr2+3*16);

    // pool -> level 2
    cudaMemsetAsync(P.bufA, 0, N2*96*sizeof(float), 0);
    cudaMemsetAsync(P.cntf, 0, N2*sizeof(float), 0);
    pool_scatter_k<<<(N1*96+255)/256, 256>>>(P.x1s, cl2, P.bufA, N1);
    pool_cnt_k<<<(N1+255)/256, 256>>>(cl2, P.cntf, N1);
    pool_div_k<<<(N2*96+255)/256, 256>>>(P.bufA, P.cntf, N2);

    // bottleneck
    run_layer(P, P.bufA, P.bufB, 2, 32, 32, WqM+3*MW, WkM+3*MW, WvM+3*MW, WsM+3*MW,
              sc_mid+4*32, bi_mid+4*32, wr1+4*16, wr2+4*16);
    run_layer(P, P.bufB, P.bufA, 2, 32, 32, WqM+4*MW, WkM+4*MW, WvM+4*MW, WsM+4*MW,
              sc_mid+5*32, bi_mid+5*32, wr1+5*16, wr2+5*16);

    // upsample -> level 1 (+ residual x1)
    cudaMemcpyAsync(P.bufB, P.x1s, N1*96*sizeof(float), cudaMemcpyDeviceToDevice, 0);
    scatter_add_k<<<(N2*96+255)/256, 256>>>(P.bufB, P.bufA, fp2, N2);

    run_layer(P, P.bufB, P.bufA, 1, 32, 32, WqM+5*MW, WkM+5*MW, WvM+5*MW, WsM+5*MW,
              sc_mid+6*32, bi_mid+6*32, wr1+6*16, wr2+6*16);
    run_layer(P, P.bufA, P.bufB, 1, 32, 32, WqM+6*MW, WkM+6*MW, WvM+6*MW, WsM+6*MW,
              sc_mid+7*32, bi_mid+7*32, wr1+7*16, wr2+7*16);

    // upsample -> level 0 (+ residual x0)
    cudaMemcpyAsync(P.bufA, P.x0s, N0*96*sizeof(float), cudaMemcpyDeviceToDevice, 0);
    scatter_add_k<<<(N1*96+255)/256, 256>>>(P.bufA, P.bufB, fp1, N1);

    run_layer(P, P.bufA, P.bufB, 0, 32, 32, WqM+7*MW, WkM+7*MW, WvM+7*MW, WsM+7*MW,
              sc_mid+8*32, bi_mid+8*32, wr1+8*16, wr2+8*16);
    run_layer(P, P.bufB, P.bufA, 0, 32, 1, WqL, WkL, WvL, WsL,
              sc_las, bi_las, wr1+9*16, wr2+9*16);

    // MLP head: [N0,3] @ [3,40] + ReLU
    mlp_k<<<(N0*40+255)/256, 256>>>(P.bufA, Wmlp, out, N0);
}

// round 7
// speedup vs baseline: 1.0970x; 1.0970x over previous
#include <cuda_runtime.h>
#include <math.h>

#define N0 32768
#define N1 8192
#define N2 2048
#define E0 (N0*8)
#define E1 (N1*8)
#define E2 (N2*8)
#define CC 32

#define RPO1 (N0+1)
#define RPO2 (N0+1+N1+1)
#define RPTOT (N0+1+N1+1+N2+1)

// ---------------- static scratch (no allocation allowed) ----------------
__device__ __align__(16) float g_bufA[N0*3*CC];
__device__ __align__(16) float g_bufB[N0*3*CC];
__device__ __align__(16) float g_x0[N0*3*CC];
__device__ __align__(16) float g_x1[N1*3*CC];
__device__ __align__(16) float g_q[N0*3*CC];
__device__ __align__(16) float g_k[N0*3*CC];
__device__ __align__(16) float g_v[N0*3*CC];
__device__ __align__(16) float g_s[N0*3*CC];
__device__ __align__(16) float g_pos1[N1*3];
__device__ __align__(16) float g_pos2[N2*3];
__device__ int g_rowptr[RPTOT];
__device__ int g_cursor[RPTOT];
__device__ int g_csrc[E0+E1+E2];
__device__ __align__(16) float4 g_crelr[E0+E1+E2];
__device__ __align__(16) float g_pool[N1*96 + N1];   // pooled sums + counts (contiguous)

// ---------------- packed f32x2 helpers ----------------
__device__ __forceinline__ unsigned long long pk2(float lo, float hi){
    unsigned long long r;
    asm("mov.b64 %0, {%1,%2};" : "=l"(r) : "f"(lo), "f"(hi));
    return r;
}
__device__ __forceinline__ unsigned long long ffma2(unsigned long long a, unsigned long long b, unsigned long long c){
    unsigned long long d;
    asm("fma.rn.f32x2 %0, %1, %2, %3;" : "=l"(d) : "l"(a), "l"(b), "l"(c));
    return d;
}
__device__ __forceinline__ float2 upk2(unsigned long long v){
    float2 r;
    asm("mov.b64 {%0,%1}, %2;" : "=f"(r.x), "=f"(r.y) : "l"(v));
    return r;
}

// ---------------- small utility kernels ----------------
__global__ void gather_pos_k(const float* __restrict__ pos, const int* __restrict__ idx,
                             float* __restrict__ out, int N){
    int i = blockIdx.x*blockDim.x + threadIdx.x;
    if (i >= N) return;
    int s = idx[i];
    out[3*i+0] = pos[3*s+0];
    out[3*i+1] = pos[3*s+1];
    out[3*i+2] = pos[3*s+2];
}

// one launch: histogram all 3 levels into g_cursor (pre-zeroed)
__global__ void hist3_k(const int* __restrict__ d0, const int* __restrict__ d1,
                        const int* __restrict__ d2, int* __restrict__ cur){
    int e = blockIdx.x*blockDim.x + threadIdx.x;
    if (e < E0)            atomicAdd(&cur[d0[e]], 1);
    else if (e < E0+E1)    atomicAdd(&cur[RPO1 + d1[e-E0]], 1);
    else if (e < E0+E1+E2) atomicAdd(&cur[RPO2 + d2[e-E0-E1]], 1);
}

// one launch, 3 blocks: block b scans level b.
// Two-pass per thread (sum chunk, block-scan partials, re-read + write) keeps
// register use ~25/thread; counts are L1/L2-resident so the re-read is free.
// Also writes cursor := rowptr (replaces the old memcpy).
__global__ void __launch_bounds__(512) scan3_k(int* __restrict__ cursor, int* __restrict__ rowptr){
    int b = blockIdx.x;
    int n   = (b==0) ? N0 : (b==1) ? N1 : N2;
    int off = (b==0) ? 0  : (b==1) ? RPO1 : RPO2;
    int* cnt = cursor + off;
    int* rp  = rowptr + off;
    int t = threadIdx.x;
    int lane = t & 31, wid = t >> 5;
    const int CH = 64;                     // 512*64 = 32768 max
    int base = t*CH;
    int hi = min(n, base+CH);
    // pass 1: chunk total
    int s = 0;
    for (int i = base; i < hi; i++) s += cnt[i];
    // block inclusive scan of 512 partials
    int inc = s;
    #pragma unroll
    for (int o = 1; o < 32; o <<= 1){
        int x = __shfl_up_sync(0xffffffffu, inc, o);
        if (lane >= o) inc += x;
    }
    __shared__ int wsum[16];
    if (lane == 31) wsum[wid] = inc;
    __syncthreads();
    if (wid == 0 && lane < 16){
        int ws = wsum[lane];
        #pragma unroll
        for (int o = 1; o < 16; o <<= 1){
            int x = __shfl_up_sync(0x0000ffffu, ws, o);
            if (lane >= o) ws += x;
        }
        wsum[lane] = ws;
    }
    __syncthreads();
    int excl = inc - s + ((wid > 0) ? wsum[wid-1] : 0);
    // pass 2: re-read chunk, write exclusive prefix into rowptr and cursor
    int run = excl;
    for (int i = base; i < hi; i++){
        int v = cnt[i];
        rp[i] = run;
        cnt[i] = run;      // cursor for build phase (safe: write-after-read same thread)
        run += v;
    }
    if (t == 511) rp[n] = wsum[15];   // grand total
}

// one launch: build CSR (source ids + rel/r in CSR order) for all 3 levels
__global__ void build3_k(const int* __restrict__ s0, const int* __restrict__ d0,
                         const int* __restrict__ s1, const int* __restrict__ d1,
                         const int* __restrict__ s2, const int* __restrict__ d2,
                         const float* __restrict__ p0, const float* __restrict__ p1,
                         const float* __restrict__ p2,
                         int* __restrict__ cursor, int* __restrict__ csrc,
                         float4* __restrict__ crelr){
    int e = blockIdx.x*blockDim.x + threadIdx.x;
    const int* srcp; const int* dstp; const float* pos;
    int rpo, eo, le;
    if (e < E0){ srcp=s0; dstp=d0; pos=p0; rpo=0;    eo=0;     le=e; }
    else if (e < E0+E1){ srcp=s1; dstp=d1; pos=p1; rpo=RPO1; eo=E0;    le=e-E0; }
    else if (e < E0+E1+E2){ srcp=s2; dstp=d2; pos=p2; rpo=RPO2; eo=E0+E1; le=e-E0-E1; }
    else return;
    int d = dstp[le];
    int s = srcp[le];
    int slot = atomicAdd(&cursor[rpo + d], 1);
    float dx = pos[3*d+0] - pos[3*s+0];
    float dy = pos[3*d+1] - pos[3*s+1];
    float dz = pos[3*d+2] - pos[3*s+2];
    float r = sqrtf(dx*dx + dy*dy + dz*dz + 1e-12f);
    csrc[eo + slot] = s;
    crelr[eo + slot] = make_float4(dx, dy, dz, r);
}

// ---------------- q,k,v,skip projection ----------------
template<int CIN, int COUT>
__global__ void qkvs_k(const float* __restrict__ x,
                       const float* __restrict__ Wq, const float* __restrict__ Wk,
                       const float* __restrict__ Wv, const float* __restrict__ Ws,
                       float* __restrict__ q, float* __restrict__ k,
                       float* __restrict__ v, float* __restrict__ sk, int rows){
    __shared__ __align__(16) float sW[4][CIN*COUT];
    {
        const float* Wsrc[4] = {Wq, Wk, Wv, Ws};
        #pragma unroll
        for (int m2 = 0; m2 < 4; m2++)
            for (int i = threadIdx.x; i < CIN*COUT; i += blockDim.x)
                sW[m2][i] = Wsrc[m2][i];
    }
    __syncthreads();
    int t = blockIdx.x*blockDim.x + threadIdx.x;
    if (t >= rows) return;
    float xr[CIN];
    #pragma unroll
    for (int c = 0; c < CIN; c++) xr[c] = x[t*CIN + c];
    float* outs[4] = {q, k, v, sk};
    #pragma unroll
    for (int m2 = 0; m2 < 4; m2++){
        if (COUT == 1){
            float acc = 0.f;
            #pragma unroll
            for (int c = 0; c < CIN; c++) acc = fmaf(xr[c], sW[m2][c], acc);
            outs[m2][t] = acc;
        } else {
            unsigned long long acc[COUT/2 > 0 ? COUT/2 : 1];
            #pragma unroll
            for (int op = 0; op < COUT/2; op++) acc[op] = 0ULL;
            #pragma unroll
            for (int c = 0; c < CIN; c++){
                unsigned long long xx = pk2(xr[c], xr[c]);
                const unsigned long long* wp =
                    reinterpret_cast<const unsigned long long*>(&sW[m2][c*COUT]);
                #pragma unroll
                for (int op = 0; op < COUT/2; op++)
                    acc[op] = ffma2(wp[op], xx, acc[op]);
            }
            float2* outp = reinterpret_cast<float2*>(outs[m2] + t*COUT);
            #pragma unroll
            for (int op = 0; op < COUT/2; op++) outp[op] = upk2(acc[op]);
        }
    }
}

// ---------------- warp-per-node attention aggregation + norm_bias ----------------
// software-pipelined: next edge's metadata prefetched; v-row loaded before the
// logit reduction so the gather overlaps the SHFL/MUFU serial chain.
template<int COUT>
__global__ void agg_k(const float* __restrict__ q, const float* __restrict__ k,
                      const float* __restrict__ v, const float* __restrict__ sk,
                      const int* __restrict__ rowptr, const int* __restrict__ csrc,
                      const float4* __restrict__ crelr,
                      const float* __restrict__ w1, const float* __restrict__ w2,
                      const float* __restrict__ scale, const float* __restrict__ bias,
                      float inv_scale, float* __restrict__ xout, int N){
    int gw = (blockIdx.x*blockDim.x + threadIdx.x) >> 5;
    int lane = threadIdx.x & 31;
    if (gw >= N) return;
    int n = gw;
    float q0 = 0.f, q1 = 0.f, q2 = 0.f;
    if (lane < COUT){
        const float* qp = q + n*3*COUT;
        q0 = qp[lane]; q1 = qp[COUT+lane]; q2 = qp[2*COUT+lane];
    }
    float w1v = 0.f, w2v = 0.f;
    if (lane < 16){ w1v = w1[lane]; w2v = w2[lane]; }
    int beg = rowptr[n], end = rowptr[n+1];
    float m = -INFINITY, ssum = 0.f, a0 = 0.f, a1 = 0.f, a2 = 0.f;

    int idx = beg;
    int s = (idx < end) ? csrc[idx] : 0;
    float4 rr = (idx < end) ? crelr[idx] : make_float4(0.f,0.f,0.f,0.f);
    while (idx < end){
        // issue all gathers for this edge up front
        float k0=0.f,k1=0.f,k2=0.f, vv0=0.f,vv1=0.f,vv2=0.f;
        if (lane < COUT){
            const float* kp = k + s*3*COUT;
            const float* vp = v + s*3*COUT;
            k0 = kp[lane]; k1 = kp[COUT+lane]; k2 = kp[2*COUT+lane];
            vv0 = vp[lane]; vv1 = vp[COUT+lane]; vv2 = vp[2*COUT+lane];
        }
        // prefetch next edge metadata
        int idxn = idx + 1;
        int sn = 0; float4 rrn = rr;
        if (idxn < end){ sn = csrc[idxn]; rrn = crelr[idxn]; }

        float part = (q0*k0 + q1*k1 + q2*k2)*inv_scale
                   + ((lane < 16) ? fmaxf(rr.w*w1v, 0.f)*w2v : 0.f);
        #pragma unroll
        for (int off = 16; off; off >>= 1) part += __shfl_xor_sync(0xffffffffu, part, off);
        float logit = part;
        float wgt;
        if (logit > m){
            float f = __expf(m - logit);
            ssum = ssum*f + 1.f;
            a0 *= f; a1 *= f; a2 *= f;
            m = logit; wgt = 1.f;
        } else {
            wgt = __expf(logit - m);
            ssum += wgt;
        }
        a0 = fmaf(wgt, vv0 + rr.x, a0);
        a1 = fmaf(wgt, vv1 + rr.y, a1);
        a2 = fmaf(wgt, vv2 + rr.z, a2);
        s = sn; rr = rrn; idx = idxn;
    }
    if (lane < COUT){
        float inv = 1.f/(ssum + 1e-9f);
        const float* sp = sk + n*3*COUT;
        float o0 = a0*inv + sp[lane];
        float o1 = a1*inv + sp[COUT+lane];
        float o2 = a2*inv + sp[2*COUT+lane];
        float nrm = sqrtf(o0*o0 + o1*o1 + o2*o2 + 1e-12f);
        float tt = fmaxf(scale[lane]*nrm + bias[lane], 0.f)/nrm;
        float* op = xout + n*3*COUT;
        op[lane]        = o0*tt;
        op[COUT+lane]   = o1*tt;
        op[2*COUT+lane] = o2*tt;
    }
}

// ---------------- pooling / upsample / head ----------------
__global__ void pool_k(const float* __restrict__ x, const int* __restrict__ cl,
                       float* __restrict__ out, float* __restrict__ cnt, int Nsrc){
    int i = blockIdx.x*blockDim.x + threadIdx.x;
    if (i >= Nsrc*96) return;
    int j = i/96, e = i - j*96;
    int c = cl[j];
    atomicAdd(&out[c*96 + e], x[i]);
    if (e == 0) atomicAdd(&cnt[c], 1.f);
}
__global__ void pool_div_k(float* __restrict__ out, const float* __restrict__ cnt, int Ndst){
    int i = blockIdx.x*blockDim.x + threadIdx.x;
    if (i >= Ndst*96) return;
    out[i] = out[i] / (cnt[i/96] + 1e-9f);
}
__global__ void scatter_add_k(float* __restrict__ out, const float* __restrict__ x,
                              const int* __restrict__ fp, int Nsrc){
    int i = blockIdx.x*blockDim.x + threadIdx.x;
    if (i >= Nsrc*96) return;
    int j = i/96, e = i - j*96;
    out[fp[j]*96 + e] += x[i];   // fp indices unique -> race-free
}
__global__ void mlp_k(const float* __restrict__ x, const float* __restrict__ W,
                      float* __restrict__ y, int N){
    int t = blockIdx.x*blockDim.x + threadIdx.x;
    if (t >= N*40) return;
    int n = t/40, o = t - n*40;
    float a = x[3*n+0]*W[o] + x[3*n+1]*W[40+o] + x[3*n+2]*W[80+o];
    y[t] = fmaxf(a, 0.f);
}

// ---------------- host orchestration ----------------
struct Ptrs {
    float *bufA, *bufB, *x0s, *x1s, *q, *k, *v, *s, *pos1, *pos2, *pool;
    int *rowptr, *cursor, *csrc;
    float4 *crelr;
};

static void run_layer(const Ptrs& P, const float* xin, float* xout, int lvl,
                      int cin, int cout,
                      const float* Wq, const float* Wk, const float* Wv, const float* Ws,
                      const float* sc, const float* bi,
                      const float* w1, const float* w2){
    int n   = (lvl == 0) ? N0 : (lvl == 1) ? N1 : N2;
    int rpo = (lvl == 0) ? 0  : (lvl == 1) ? RPO1 : RPO2;
    int eo  = (lvl == 0) ? 0  : (lvl == 1) ? E0 : (E0+E1);
    int rows = n*3;
    if (cin == 1)
        qkvs_k<1,32><<<(rows+127)/128, 128>>>(xin, Wq, Wk, Wv, Ws, P.q, P.k, P.v, P.s, rows);
    else if (cout == 32)
        qkvs_k<32,32><<<(rows+127)/128, 128>>>(xin, Wq, Wk, Wv, Ws, P.q, P.k, P.v, P.s, rows);
    else
        qkvs_k<32,1><<<(rows+127)/128, 128>>>(xin, Wq, Wk, Wv, Ws, P.q, P.k, P.v, P.s, rows);
    float invs = 1.f/sqrtf(3.f*(float)cout);
    if (cout == 32)
        agg_k<32><<<n/8, 256>>>(P.q, P.k, P.v, P.s, P.rowptr+rpo, P.csrc+eo, P.crelr+eo,
                                w1, w2, sc, bi, invs, xout, n);
    else
        agg_k<1><<<n/8, 256>>>(P.q, P.k, P.v, P.s, P.rowptr+rpo, P.csrc+eo, P.crelr+eo,
                               w1, w2, sc, bi, invs, xout, n);
}

extern "C" void kernel_launch(void* const* d_in, const int* in_sizes, int n_in,
                              void* d_out, int out_size){
    const float* pos0   = (const float*)d_in[0];
    const float* v0     = (const float*)d_in[1];
    const float* WqF    = (const float*)d_in[2];
    const float* WkF    = (const float*)d_in[3];
    const float* WvF    = (const float*)d_in[4];
    const float* WsF    = (const float*)d_in[5];
    const float* WqM    = (const float*)d_in[6];
    const float* WkM    = (const float*)d_in[7];
    const float* WvM    = (const float*)d_in[8];
    const float* WsM    = (const float*)d_in[9];
    const float* WqL    = (const float*)d_in[10];
    const float* WkL    = (const float*)d_in[11];
    const float* WvL    = (const float*)d_in[12];
    const float* WsL    = (const float*)d_in[13];
    const float* wr1    = (const float*)d_in[14];
    const float* wr2    = (const float*)d_in[15];
    const float* sc_mid = (const float*)d_in[16];
    const float* bi_mid = (const float*)d_in[17];
    const float* sc_las = (const float*)d_in[18];
    const float* bi_las = (const float*)d_in[19];
    const float* Wmlp   = (const float*)d_in[20];
    const int* src0 = (const int*)d_in[21];
    const int* dst0 = (const int*)d_in[22];
    const int* src1 = (const int*)d_in[23];
    const int* dst1 = (const int*)d_in[24];
    const int* src2 = (const int*)d_in[25];
    const int* dst2 = (const int*)d_in[26];
    const int* fp1  = (const int*)d_in[27];
    const int* fp2  = (const int*)d_in[28];
    const int* cl1  = (const int*)d_in[29];
    const int* cl2  = (const int*)d_in[30];
    float* out = (float*)d_out;

    Ptrs P;
    cudaGetSymbolAddress((void**)&P.bufA, g_bufA);
    cudaGetSymbolAddress((void**)&P.bufB, g_bufB);
    cudaGetSymbolAddress((void**)&P.x0s,  g_x0);
    cudaGetSymbolAddress((void**)&P.x1s,  g_x1);
    cudaGetSymbolAddress((void**)&P.q,    g_q);
    cudaGetSymbolAddress((void**)&P.k,    g_k);
    cudaGetSymbolAddress((void**)&P.v,    g_v);
    cudaGetSymbolAddress((void**)&P.s,    g_s);
    cudaGetSymbolAddress((void**)&P.pos1, g_pos1);
    cudaGetSymbolAddress((void**)&P.pos2, g_pos2);
    cudaGetSymbolAddress((void**)&P.pool, g_pool);
    cudaGetSymbolAddress((void**)&P.rowptr, g_rowptr);
    cudaGetSymbolAddress((void**)&P.cursor, g_cursor);
    cudaGetSymbolAddress((void**)&P.csrc,   g_csrc);
    cudaGetSymbolAddress((void**)&P.crelr,  g_crelr);

    // geometry for levels 1 and 2
    gather_pos_k<<<(N1+255)/256, 256>>>(pos0, fp1, P.pos1, N1);
    gather_pos_k<<<(N2+255)/256, 256>>>(P.pos1, fp2, P.pos2, N2);

    // CSR build for all 3 levels: 4 launches total
    cudaMemsetAsync(P.cursor, 0, RPTOT*sizeof(int), 0);
    {
        int ET = E0+E1+E2;
        hist3_k<<<(ET+255)/256, 256>>>(dst0, dst1, dst2, P.cursor);
        scan3_k<<<3, 512>>>(P.cursor, P.rowptr);
        build3_k<<<(ET+255)/256, 256>>>(src0, dst0, src1, dst1, src2, dst2,
                                        pos0, P.pos1, P.pos2,
                                        P.cursor, P.csrc, P.crelr);
    }

    const int MW = 1024; // 32*32 mid-weight stride

    // down block 0 (level 0)
    run_layer(P, v0,     P.bufA, 0, 1, 32, WqF, WkF, WvF, WsF,
              sc_mid+0,  bi_mid+0,  wr1+0,  wr2+0);
    run_layer(P, P.bufA, P.x0s,  0, 32, 32, WqM+0*MW, WkM+0*MW, WvM+0*MW, WsM+0*MW,
              sc_mid+32, bi_mid+32, wr1+16, wr2+16);

    // pool -> level 1  (pool buffer layout: [N1*96 sums][N1 counts], one memset)
    cudaMemsetAsync(P.pool, 0, (N1*96 + N1)*sizeof(float), 0);
    pool_k<<<(N0*96+255)/256, 256>>>(P.x0s, cl1, P.pool, P.pool + N1*96, N0);
    pool_div_k<<<(N1*96+255)/256, 256>>>(P.pool, P.pool + N1*96, N1);

    run_layer(P, P.pool, P.bufB, 1, 32, 32, WqM+1*MW, WkM+1*MW, WvM+1*MW, WsM+1*MW,
              sc_mid+2*32, bi_mid+2*32, wr1+2*16, wr2+2*16);
    run_layer(P, P.bufB, P.x1s,  1, 32, 32, WqM+2*MW, WkM+2*MW, WvM+2*MW, WsM+2*MW,
              sc_mid+3*32, bi_mid+3*32, wr1+3*16, wr2+3*16);

    // pool -> level 2
    cudaMemsetAsync(P.pool, 0, (N2*96 + N2)*sizeof(float), 0);
    pool_k<<<(N1*96+255)/256, 256>>>(P.x1s, cl2, P.pool, P.pool + N2*96, N1);
    pool_div_k<<<(N2*96+255)/256, 256>>>(P.pool, P.pool + N2*96, N2);

    // bottleneck
    run_layer(P, P.pool, P.bufB, 2, 32, 32, WqM+3*MW, WkM+3*MW, WvM+3*MW, WsM+3*MW,
              sc_mid+4*32, bi_mid+4*32, wr1+4*16, wr2+4*16);
    run_layer(P, P.bufB, P.bufA, 2, 32, 32, WqM+4*MW, WkM+4*MW, WvM+4*MW, WsM+4*MW,
              sc_mid+5*32, bi_mid+5*32, wr1+5*16, wr2+5*16);

    // upsample -> level 1 (+ residual x1)
    cudaMemcpyAsync(P.bufB, P.x1s, N1*96*sizeof(float), cudaMemcpyDeviceToDevice, 0);
    scatter_add_k<<<(N2*96+255)/256, 256>>>(P.bufB, P.bufA, fp2, N2);

    run_layer(P, P.bufB, P.bufA, 1, 32, 32, WqM+5*MW, WkM+5*MW, WvM+5*MW, WsM+5*MW,
              sc_mid+6*32, bi_mid+6*32, wr1+6*16, wr2+6*16);
    run_layer(P, P.bufA, P.bufB, 1, 32, 32, WqM+6*MW, WkM+6*MW, WvM+6*MW, WsM+6*MW,
              sc_mid+7*32, bi_mid+7*32, wr1+7*16, wr2+7*16);

    // upsample -> level 0 (+ residual x0)
    cudaMemcpyAsync(P.bufA, P.x0s, N0*96*sizeof(float), cudaMemcpyDeviceToDevice, 0);
    scatter_add_k<<<(N1*96+255)/256, 256>>>(P.bufA, P.bufB, fp1, N1);

    run_layer(P, P.bufA, P.bufB, 0, 32, 32, WqM+7*MW, WkM+7*MW, WvM+7*MW, WsM+7*MW,
              sc_mid+8*32, bi_mid+8*32, wr1+8*16, wr2+8*16);
    run_layer(P, P.bufB, P.bufA, 0, 32, 1, WqL, WkL, WvL, WsL,
              sc_las, bi_las, wr1+9*16, wr2+9*16);

    // MLP head: [N0,3] @ [3,40] + ReLU
    mlp_k<<<(N0*40+255)/256, 256>>>(P.bufA, Wmlp, out, N0);
}

// round 10
// speedup vs baseline: 1.1171x; 1.0183x over previous
#include <cuda_runtime.h>
#include <math.h>

#define N0 32768
#define N1 8192
#define N2 2048
#define E0 (N0*8)
#define E1 (N1*8)
#define E2 (N2*8)
#define CC 32

#define RPO1 (N0+1)
#define RPO2 (N0+1+N1+1)
#define RPTOT (N0+1+N1+1+N2+1)

// ---------------- static scratch (no allocation allowed) ----------------
__device__ __align__(16) float g_bufA[N0*3*CC];
__device__ __align__(16) float g_bufB[N0*3*CC];
__device__ __align__(16) float g_x0[N0*3*CC];
__device__ __align__(16) float g_x1[N1*3*CC];
__device__ __align__(16) float g_q[N0*3*CC];
__device__ __align__(16) float g_k[N0*3*CC];
__device__ __align__(16) float g_v[N0*3*CC];
__device__ __align__(16) float g_s[N0*3*CC];
__device__ __align__(16) float g_pos1[N1*3];
__device__ __align__(16) float g_pos2[N2*3];
__device__ int g_rowptr[RPTOT];
__device__ int g_cursor[RPTOT];
__device__ int g_csrc[E0+E1+E2];
__device__ __align__(16) float4 g_crelr[E0+E1+E2];
__device__ __align__(16) float g_pool[N1*96 + N1];   // pooled sums + counts (contiguous)
__device__ int g_inv[N0 + N1];                       // inv1[N0], inv2[N1]

// ---------------- packed f32x2 helpers ----------------
__device__ __forceinline__ unsigned long long pk2(float lo, float hi){
    unsigned long long r;
    asm("mov.b64 %0, {%1,%2};" : "=l"(r) : "f"(lo), "f"(hi));
    return r;
}
__device__ __forceinline__ unsigned long long ffma2(unsigned long long a, unsigned long long b, unsigned long long c){
    unsigned long long d;
    asm("fma.rn.f32x2 %0, %1, %2, %3;" : "=l"(d) : "l"(a), "l"(b), "l"(c));
    return d;
}
__device__ __forceinline__ float2 upk2(unsigned long long v){
    float2 r;
    asm("mov.b64 {%0,%1}, %2;" : "=f"(r.x), "=f"(r.y) : "l"(v));
    return r;
}

// ---------------- small utility kernels ----------------
// gathers positions AND builds the inverse map (inv[fp[i]] = i) in one pass
__global__ void gather_pos_k(const float* __restrict__ pos, const int* __restrict__ idx,
                             float* __restrict__ out, int* __restrict__ inv, int N){
    int i = blockIdx.x*blockDim.x + threadIdx.x;
    if (i >= N) return;
    int s = idx[i];
    out[3*i+0] = pos[3*s+0];
    out[3*i+1] = pos[3*s+1];
    out[3*i+2] = pos[3*s+2];
    inv[s] = i;
}

// one launch: histogram all 3 levels into g_cursor (pre-zeroed)
__global__ void hist3_k(const int* __restrict__ d0, const int* __restrict__ d1,
                        const int* __restrict__ d2, int* __restrict__ cur){
    int e = blockIdx.x*blockDim.x + threadIdx.x;
    if (e < E0)            atomicAdd(&cur[d0[e]], 1);
    else if (e < E0+E1)    atomicAdd(&cur[RPO1 + d1[e-E0]], 1);
    else if (e < E0+E1+E2) atomicAdd(&cur[RPO2 + d2[e-E0-E1]], 1);
}

// one launch, 3 blocks: block b scans level b. 1024 threads x 32-element chunks,
// fully unrolled so all 32 loads issue back-to-back (one latency exposure, not 32).
// Level sizes are multiples of 32 -> whole-chunk predication only.
// Also writes cursor := rowptr (cursor doubles as build-phase slot counter).
__global__ void __launch_bounds__(1024) scan3_k(int* __restrict__ cursor, int* __restrict__ rowptr){
    int b = blockIdx.x;
    int n   = (b==0) ? N0 : (b==1) ? N1 : N2;
    int off = (b==0) ? 0  : (b==1) ? RPO1 : RPO2;
    int* cnt = cursor + off;
    int* rp  = rowptr + off;
    int t = threadIdx.x;
    int lane = t & 31, wid = t >> 5;
    int base = t*32;
    bool active = base < n;
    // pass 1: chunk total, batched loads
    int s = 0;
    if (active){
        int vv[32];
        #pragma unroll
        for (int u = 0; u < 32; u++) vv[u] = cnt[base+u];
        #pragma unroll
        for (int u = 0; u < 32; u++) s += vv[u];
    }
    // 32-warp block scan
    int inc = s;
    #pragma unroll
    for (int o = 1; o < 32; o <<= 1){
        int x = __shfl_up_sync(0xffffffffu, inc, o);
        if (lane >= o) inc += x;
    }
    __shared__ int wsum[32];
    if (lane == 31) wsum[wid] = inc;
    __syncthreads();
    if (wid == 0){
        int ws = wsum[lane];
        #pragma unroll
        for (int o = 1; o < 32; o <<= 1){
            int x = __shfl_up_sync(0xffffffffu, ws, o);
            if (lane >= o) ws += x;
        }
        wsum[lane] = ws;
    }
    __syncthreads();
    int excl = inc - s + ((wid > 0) ? wsum[wid-1] : 0);
    // pass 2: re-read (L1-hot), write exclusive prefix into rowptr and cursor
    if (active){
        int vv[32];
        #pragma unroll
        for (int u = 0; u < 32; u++) vv[u] = cnt[base+u];
        int run = excl;
        #pragma unroll
        for (int u = 0; u < 32; u++){
            rp[base+u]  = run;
            cnt[base+u] = run;
            run += vv[u];
        }
    }
    if (t == 0) rp[n] = wsum[31];   // grand total (inactive warps contributed 0)
}

// one launch: build CSR (source ids + rel/r in CSR order) for all 3 levels
__global__ void build3_k(const int* __restrict__ s0, const int* __restrict__ d0,
                         const int* __restrict__ s1, const int* __restrict__ d1,
                         const int* __restrict__ s2, const int* __restrict__ d2,
                         const float* __restrict__ p0, const float* __restrict__ p1,
                         const float* __restrict__ p2,
                         int* __restrict__ cursor, int* __restrict__ csrc,
                         float4* __restrict__ crelr){
    int e = blockIdx.x*blockDim.x + threadIdx.x;
    const int* srcp; const int* dstp; const float* pos;
    int rpo, eo, le;
    if (e < E0){ srcp=s0; dstp=d0; pos=p0; rpo=0;    eo=0;     le=e; }
    else if (e < E0+E1){ srcp=s1; dstp=d1; pos=p1; rpo=RPO1; eo=E0;    le=e-E0; }
    else if (e < E0+E1+E2){ srcp=s2; dstp=d2; pos=p2; rpo=RPO2; eo=E0+E1; le=e-E0-E1; }
    else return;
    int d = dstp[le];
    int s = srcp[le];
    int slot = atomicAdd(&cursor[rpo + d], 1);
    float dx = pos[3*d+0] - pos[3*s+0];
    float dy = pos[3*d+1] - pos[3*s+1];
    float dz = pos[3*d+2] - pos[3*s+2];
    float r = sqrtf(dx*dx + dy*dy + dz*dz + 1e-12f);
    csrc[eo + slot] = s;
    crelr[eo + slot] = make_float4(dx, dy, dz, r);
}

// ---------------- q,k,v,skip projection (with fused input combiner) ----------------
// MODE 0: x = base
// MODE 1: x = base / (cnt[node] + eps)          (pooled mean)
// MODE 2: x = base + (inv[node]>=0 ? add[..] : 0)  (upsample scatter + residual)
template<int CIN, int COUT, int MODE>
__global__ void qkvs_k(const float* __restrict__ base,
                       const float* __restrict__ aux_f,   // cnt (MODE1) or add (MODE2)
                       const int* __restrict__ inv,       // MODE2
                       const float* __restrict__ Wq, const float* __restrict__ Wk,
                       const float* __restrict__ Wv, const float* __restrict__ Ws,
                       float* __restrict__ q, float* __restrict__ k,
                       float* __restrict__ v, float* __restrict__ sk, int rows){
    __shared__ __align__(16) float sW[4][CIN*COUT];
    {
        const float* Wsrc[4] = {Wq, Wk, Wv, Ws};
        #pragma unroll
        for (int m2 = 0; m2 < 4; m2++)
            for (int i = threadIdx.x; i < CIN*COUT; i += blockDim.x)
                sW[m2][i] = Wsrc[m2][i];
    }
    __syncthreads();
    int t = blockIdx.x*blockDim.x + threadIdx.x;
    if (t >= rows) return;
    float xr[CIN];
    #pragma unroll
    for (int c = 0; c < CIN; c++) xr[c] = base[t*CIN + c];
    if (MODE == 1){
        float invc = 1.f/(aux_f[t/3] + 1e-9f);
        #pragma unroll
        for (int c = 0; c < CIN; c++) xr[c] *= invc;
    } else if (MODE == 2){
        int node = t/3, vc = t - node*3;
        int j = inv[node];
        if (j >= 0){
            const float* ap = aux_f + (j*3 + vc)*CIN;
            #pragma unroll
            for (int c = 0; c < CIN; c++) xr[c] += ap[c];
        }
    }
    float* outs[4] = {q, k, v, sk};
    #pragma unroll
    for (int m2 = 0; m2 < 4; m2++){
        if (COUT == 1){
            float acc = 0.f;
            #pragma unroll
            for (int c = 0; c < CIN; c++) acc = fmaf(xr[c], sW[m2][c], acc);
            outs[m2][t] = acc;
        } else {
            unsigned long long acc[COUT/2 > 0 ? COUT/2 : 1];
            #pragma unroll
            for (int op = 0; op < COUT/2; op++) acc[op] = 0ULL;
            #pragma unroll
            for (int c = 0; c < CIN; c++){
                unsigned long long xx = pk2(xr[c], xr[c]);
                const unsigned long long* wp =
                    reinterpret_cast<const unsigned long long*>(&sW[m2][c*COUT]);
                #pragma unroll
                for (int op = 0; op < COUT/2; op++)
                    acc[op] = ffma2(wp[op], xx, acc[op]);
            }
            float2* outp = reinterpret_cast<float2*>(outs[m2] + t*COUT);
            #pragma unroll
            for (int op = 0; op < COUT/2; op++) outp[op] = upk2(acc[op]);
        }
    }
}

// ---------------- warp-per-node attention aggregation + norm_bias ----------------
template<int COUT>
__global__ void agg_k(const float* __restrict__ q, const float* __restrict__ k,
                      const float* __restrict__ v, const float* __restrict__ sk,
                      const int* __restrict__ rowptr, const int* __restrict__ csrc,
                      const float4* __restrict__ crelr,
                      const float* __restrict__ w1, const float* __restrict__ w2,
                      const float* __restrict__ scale, const float* __restrict__ bias,
                      float inv_scale, float* __restrict__ xout, int N){
    int gw = (blockIdx.x*blockDim.x + threadIdx.x) >> 5;
    int lane = threadIdx.x & 31;
    if (gw >= N) return;
    int n = gw;
    float q0 = 0.f, q1 = 0.f, q2 = 0.f;
    if (lane < COUT){
        const float* qp = q + n*3*COUT;
        q0 = qp[lane]*inv_scale; q1 = qp[COUT+lane]*inv_scale; q2 = qp[2*COUT+lane]*inv_scale;
    }
    float w1v = 0.f, w2v = 0.f;
    if (lane < 16){ w1v = w1[lane]; w2v = w2[lane]; }
    int beg = rowptr[n], end = rowptr[n+1];
    float m = -INFINITY, ssum = 0.f, a0 = 0.f, a1 = 0.f, a2 = 0.f;

    int idx = beg;
    int s = (idx < end) ? csrc[idx] : 0;
    float4 rr = (idx < end) ? crelr[idx] : make_float4(0.f,0.f,0.f,0.f);
    while (idx < end){
        float k0=0.f,k1=0.f,k2=0.f, vv0=0.f,vv1=0.f,vv2=0.f;
        if (lane < COUT){
            const float* kp = k + s*3*COUT;
            const float* vp = v + s*3*COUT;
            k0 = kp[lane]; k1 = kp[COUT+lane]; k2 = kp[2*COUT+lane];
            vv0 = vp[lane]; vv1 = vp[COUT+lane]; vv2 = vp[2*COUT+lane];
        }
        int idxn = idx + 1;
        int sn = 0; float4 rrn = rr;
        if (idxn < end){ sn = csrc[idxn]; rrn = crelr[idxn]; }

        float part = (q0*k0 + q1*k1 + q2*k2)
                   + ((lane < 16) ? fmaxf(rr.w*w1v, 0.f)*w2v : 0.f);
        #pragma unroll
        for (int off = 16; off; off >>= 1) part += __shfl_xor_sync(0xffffffffu, part, off);
        float logit = part;
        float wgt;
        if (logit > m){
            float f = __expf(m - logit);
            ssum = ssum*f + 1.f;
            a0 *= f; a1 *= f; a2 *= f;
            m = logit; wgt = 1.f;
        } else {
            wgt = __expf(logit - m);
            ssum += wgt;
        }
        a0 = fmaf(wgt, vv0 + rr.x, a0);
        a1 = fmaf(wgt, vv1 + rr.y, a1);
        a2 = fmaf(wgt, vv2 + rr.z, a2);
        s = sn; rr = rrn; idx = idxn;
    }
    if (lane < COUT){
        float inv = 1.f/(ssum + 1e-9f);
        const float* sp = sk + n*3*COUT;
        float o0 = a0*inv + sp[lane];
        float o1 = a1*inv + sp[COUT+lane];
        float o2 = a2*inv + sp[2*COUT+lane];
        float nrm = sqrtf(o0*o0 + o1*o1 + o2*o2 + 1e-12f);
        float tt = fmaxf(scale[lane]*nrm + bias[lane], 0.f)/nrm;
        float* op = xout + n*3*COUT;
        op[lane]        = o0*tt;
        op[COUT+lane]   = o1*tt;
        op[2*COUT+lane] = o2*tt;
    }
}

// ---------------- pooling / head ----------------
__global__ void pool_k(const float* __restrict__ x, const int* __restrict__ cl,
                       float* __restrict__ out, float* __restrict__ cnt, int Nsrc){
    int i = blockIdx.x*blockDim.x + threadIdx.x;
    if (i >= Nsrc*96) return;
    int j = i/96, e = i - j*96;
    int c = cl[j];
    atomicAdd(&out[c*96 + e], x[i]);
    if (e == 0) atomicAdd(&cnt[c], 1.f);
}
__global__ void mlp_k(const float* __restrict__ x, const float* __restrict__ W,
                      float* __restrict__ y, int N){
    int t = blockIdx.x*blockDim.x + threadIdx.x;
    if (t >= N*40) return;
    int n = t/40, o = t - n*40;
    float a = x[3*n+0]*W[o] + x[3*n+1]*W[40+o] + x[3*n+2]*W[80+o];
    y[t] = fmaxf(a, 0.f);
}

// ---------------- host orchestration ----------------
struct Ptrs {
    float *bufA, *bufB, *x0s, *x1s, *q, *k, *v, *s, *pos1, *pos2, *pool;
    int *rowptr, *cursor, *csrc, *inv;
    float4 *crelr;
};

// mode: 0 plain, 1 pooled-mean (aux=cnt), 2 upsample (aux=add, inv)
static void run_layer(const Ptrs& P, const float* xin, float* xout, int lvl,
                      int cin, int cout, int mode,
                      const float* aux_f, const int* inv,
                      const float* Wq, const float* Wk, const float* Wv, const float* Ws,
                      const float* sc, const float* bi,
                      const float* w1, const float* w2){
    int n   = (lvl == 0) ? N0 : (lvl == 1) ? N1 : N2;
    int rpo = (lvl == 0) ? 0  : (lvl == 1) ? RPO1 : RPO2;
    int eo  = (lvl == 0) ? 0  : (lvl == 1) ? E0 : (E0+E1);
    int rows = n*3;
    int gb = (rows+127)/128;
    if (cin == 1)
        qkvs_k<1,32,0><<<gb,128>>>(xin, nullptr, nullptr, Wq, Wk, Wv, Ws, P.q, P.k, P.v, P.s, rows);
    else if (cout == 1)
        qkvs_k<32,1,0><<<gb,128>>>(xin, nullptr, nullptr, Wq, Wk, Wv, Ws, P.q, P.k, P.v, P.s, rows);
    else if (mode == 0)
        qkvs_k<32,32,0><<<gb,128>>>(xin, nullptr, nullptr, Wq, Wk, Wv, Ws, P.q, P.k, P.v, P.s, rows);
    else if (mode == 1)
        qkvs_k<32,32,1><<<gb,128>>>(xin, aux_f, nullptr, Wq, Wk, Wv, Ws, P.q, P.k, P.v, P.s, rows);
    else
        qkvs_k<32,32,2><<<gb,128>>>(xin, aux_f, inv, Wq, Wk, Wv, Ws, P.q, P.k, P.v, P.s, rows);
    float invs = 1.f/sqrtf(3.f*(float)cout);
    if (cout == 32)
        agg_k<32><<<n/8, 256>>>(P.q, P.k, P.v, P.s, P.rowptr+rpo, P.csrc+eo, P.crelr+eo,
                                w1, w2, sc, bi, invs, xout, n);
    else
        agg_k<1><<<n/8, 256>>>(P.q, P.k, P.v, P.s, P.rowptr+rpo, P.csrc+eo, P.crelr+eo,
                               w1, w2, sc, bi, invs, xout, n);
}

extern "C" void kernel_launch(void* const* d_in, const int* in_sizes, int n_in,
                              void* d_out, int out_size){
    const float* pos0   = (const float*)d_in[0];
    const float* v0     = (const float*)d_in[1];
    const float* WqF    = (const float*)d_in[2];
    const float* WkF    = (const float*)d_in[3];
    const float* WvF    = (const float*)d_in[4];
    const float* WsF    = (const float*)d_in[5];
    const float* WqM    = (const float*)d_in[6];
    const float* WkM    = (const float*)d_in[7];
    const float* WvM    = (const float*)d_in[8];
    const float* WsM    = (const float*)d_in[9];
    const float* WqL    = (const float*)d_in[10];
    const float* WkL    = (const float*)d_in[11];
    const float* WvL    = (const float*)d_in[12];
    const float* WsL    = (const float*)d_in[13];
    const float* wr1    = (const float*)d_in[14];
    const float* wr2    = (const float*)d_in[15];
    const float* sc_mid = (const float*)d_in[16];
    const float* bi_mid = (const float*)d_in[17];
    const float* sc_las = (const float*)d_in[18];
    const float* bi_las = (const float*)d_in[19];
    const float* Wmlp   = (const float*)d_in[20];
    const int* src0 = (const int*)d_in[21];
    const int* dst0 = (const int*)d_in[22];
    const int* src1 = (const int*)d_in[23];
    const int* dst1 = (const int*)d_in[24];
    const int* src2 = (const int*)d_in[25];
    const int* dst2 = (const int*)d_in[26];
    const int* fp1  = (const int*)d_in[27];
    const int* fp2  = (const int*)d_in[28];
    const int* cl1  = (const int*)d_in[29];
    const int* cl2  = (const int*)d_in[30];
    float* out = (float*)d_out;

    Ptrs P;
    cudaGetSymbolAddress((void**)&P.bufA, g_bufA);
    cudaGetSymbolAddress((void**)&P.bufB, g_bufB);
    cudaGetSymbolAddress((void**)&P.x0s,  g_x0);
    cudaGetSymbolAddress((void**)&P.x1s,  g_x1);
    cudaGetSymbolAddress((void**)&P.q,    g_q);
    cudaGetSymbolAddress((void**)&P.k,    g_k);
    cudaGetSymbolAddress((void**)&P.v,    g_v);
    cudaGetSymbolAddress((void**)&P.s,    g_s);
    cudaGetSymbolAddress((void**)&P.pos1, g_pos1);
    cudaGetSymbolAddress((void**)&P.pos2, g_pos2);
    cudaGetSymbolAddress((void**)&P.pool, g_pool);
    cudaGetSymbolAddress((void**)&P.rowptr, g_rowptr);
    cudaGetSymbolAddress((void**)&P.cursor, g_cursor);
    cudaGetSymbolAddress((void**)&P.csrc,   g_csrc);
    cudaGetSymbolAddress((void**)&P.inv,    g_inv);
    cudaGetSymbolAddress((void**)&P.crelr,  g_crelr);

    int* inv1 = P.inv;        // [N0]: level0 node -> level1 slot (or -1)
    int* inv2 = P.inv + N0;   // [N1]: level1 node -> level2 slot (or -1)

    // setup: inverse maps + downsampled positions
    cudaMemsetAsync(P.inv, 0xFF, (N0+N1)*sizeof(int), 0);
    gather_pos_k<<<(N1+255)/256, 256>>>(pos0, fp1, P.pos1, inv1, N1);
    gather_pos_k<<<(N2+255)/256, 256>>>(P.pos1, fp2, P.pos2, inv2, N2);

    // CSR build for all 3 levels
    cudaMemsetAsync(P.cursor, 0, RPTOT*sizeof(int), 0);
    {
        int ET = E0+E1+E2;
        hist3_k<<<(ET+255)/256, 256>>>(dst0, dst1, dst2, P.cursor);
        scan3_k<<<3, 1024>>>(P.cursor, P.rowptr);
        build3_k<<<(ET+255)/256, 256>>>(src0, dst0, src1, dst1, src2, dst2,
                                        pos0, P.pos1, P.pos2,
                                        P.cursor, P.csrc, P.crelr);
    }

    const int MW = 1024; // 32*32 mid-weight stride

    // down block 0 (level 0)
    run_layer(P, v0,     P.bufA, 0, 1, 32, 0, nullptr, nullptr, WqF, WkF, WvF, WsF,
              sc_mid+0,  bi_mid+0,  wr1+0,  wr2+0);
    run_layer(P, P.bufA, P.x0s,  0, 32, 32, 0, nullptr, nullptr,
              WqM+0*MW, WkM+0*MW, WvM+0*MW, WsM+0*MW,
              sc_mid+32, bi_mid+32, wr1+16, wr2+16);

    // pool -> level 1  ([N1*96 sums][N1 counts], one memset; mean folded into qkvs)
    cudaMemsetAsync(P.pool, 0, (N1*96 + N1)*sizeof(float), 0);
    pool_k<<<(N0*96+255)/256, 256>>>(P.x0s, cl1, P.pool, P.pool + N1*96, N0);

    run_layer(P, P.pool, P.bufB, 1, 32, 32, 1, P.pool + N1*96, nullptr,
              WqM+1*MW, WkM+1*MW, WvM+1*MW, WsM+1*MW,
              sc_mid+2*32, bi_mid+2*32, wr1+2*16, wr2+2*16);
    run_layer(P, P.bufB, P.x1s,  1, 32, 32, 0, nullptr, nullptr,
              WqM+2*MW, WkM+2*MW, WvM+2*MW, WsM+2*MW,
              sc_mid+3*32, bi_mid+3*32, wr1+3*16, wr2+3*16);

    // pool -> level 2
    cudaMemsetAsync(P.pool, 0, (N2*96 + N2)*sizeof(float), 0);
    pool_k<<<(N1*96+255)/256, 256>>>(P.x1s, cl2, P.pool, P.pool + N2*96, N1);

    // bottleneck
    run_layer(P, P.pool, P.bufB, 2, 32, 32, 1, P.pool + N2*96, nullptr,
              WqM+3*MW, WkM+3*MW, WvM+3*MW, WsM+3*MW,
              sc_mid+4*32, bi_mid+4*32, wr1+4*16, wr2+4*16);
    run_layer(P, P.bufB, P.bufA, 2, 32, 32, 0, nullptr, nullptr,
              WqM+4*MW, WkM+4*MW, WvM+4*MW, WsM+4*MW,
              sc_mid+5*32, bi_mid+5*32, wr1+5*16, wr2+5*16);

    // up block 0 (level 1): input = x1s + scatter(bufA via inv2), fused in qkvs
    run_layer(P, P.x1s, P.bufB, 1, 32, 32, 2, P.bufA, inv2,
              WqM+5*MW, WkM+5*MW, WvM+5*MW, WsM+5*MW,
              sc_mid+6*32, bi_mid+6*32, wr1+6*16, wr2+6*16);
    run_layer(P, P.bufB, P.bufA, 1, 32, 32, 0, nullptr, nullptr,
              WqM+6*MW, WkM+6*MW, WvM+6*MW, WsM+6*MW,
              sc_mid+7*32, bi_mid+7*32, wr1+7*16, wr2+7*16);

    // up block 1 (level 0): input = x0s + scatter(bufA via inv1), fused in qkvs
    run_layer(P, P.x0s, P.bufB, 0, 32, 32, 2, P.bufA, inv1,
              WqM+7*MW, WkM+7*MW, WvM+7*MW, WsM+7*MW,
              sc_mid+8*32, bi_mid+8*32, wr1+8*16, wr2+8*16);
    run_layer(P, P.bufB, P.bufA, 0, 32, 1, 0, nullptr, nullptr, WqL, WkL, WvL, WsL,
              sc_las, bi_las, wr1+9*16, wr2+9*16);

    // MLP head: [N0,3] @ [3,40] + ReLU
    mlp_k<<<(N0*40+255)/256, 256>>>(P.bufA, Wmlp, out, N0);
}

// round 12
// speedup vs baseline: 1.3786x; 1.2340x over previous
#include <cuda_runtime.h>
#include <math.h>

#define N0 32768
#define N1 8192
#define N2 2048
#define E0 (N0*8)
#define E1 (N1*8)
#define E2 (N2*8)
#define CC 32

#define RPO1 (N0+1)
#define RPO2 (N0+1+N1+1)
#define RPTOT (N0+1+N1+1+N2+1)

// ---------------- static scratch (no allocation allowed) ----------------
__device__ __align__(16) float g_bufA[N0*3*CC];
__device__ __align__(16) float g_bufB[N0*3*CC];
__device__ __align__(16) float g_x0[N0*3*CC];
__device__ __align__(16) float g_x1[N1*3*CC];
__device__ __align__(16) float g_q[N0*3*CC];
__device__ __align__(16) float g_k[N0*3*CC];
__device__ __align__(16) float g_v[N0*3*CC];
__device__ __align__(16) float g_s[N0*3*CC];
__device__ __align__(16) float g_pos1[N1*3];
__device__ __align__(16) float g_pos2[N2*3];
__device__ int g_rowptr[RPTOT];
__device__ int g_cursor[RPTOT];
__device__ int g_csrc[E0+E1+E2];
__device__ __align__(16) float4 g_crelr[E0+E1+E2];
__device__ __align__(16) float g_pool[N1*96 + N1];   // pooled sums + counts (contiguous)
__device__ int g_inv[N0 + N1];                       // inv1[N0], inv2[N1]

// ---------------- packed f32x2 helpers ----------------
__device__ __forceinline__ unsigned long long pk2(float lo, float hi){
    unsigned long long r;
    asm("mov.b64 %0, {%1,%2};" : "=l"(r) : "f"(lo), "f"(hi));
    return r;
}
__device__ __forceinline__ unsigned long long ffma2(unsigned long long a, unsigned long long b, unsigned long long c){
    unsigned long long d;
    asm("fma.rn.f32x2 %0, %1, %2, %3;" : "=l"(d) : "l"(a), "l"(b), "l"(c));
    return d;
}
__device__ __forceinline__ float2 upk2(unsigned long long v){
    float2 r;
    asm("mov.b64 {%0,%1}, %2;" : "=f"(r.x), "=f"(r.y) : "l"(v));
    return r;
}

// ---------------- setup: both position gathers + inverse maps, one launch ----
// pos2 composed directly from pos0 (pos2[i] = pos0[fp1[fp2[i]]]) -> no dependency
__global__ void setup_k(const float* __restrict__ pos0,
                        const int* __restrict__ fp1, const int* __restrict__ fp2,
                        float* __restrict__ pos1, float* __restrict__ pos2,
                        int* __restrict__ inv1, int* __restrict__ inv2){
    int i = blockIdx.x*blockDim.x + threadIdx.x;
    if (i < N1){
        int s = fp1[i];
        pos1[3*i+0] = pos0[3*s+0];
        pos1[3*i+1] = pos0[3*s+1];
        pos1[3*i+2] = pos0[3*s+2];
        inv1[s] = i;
    } else if (i < N1+N2){
        int j = i - N1;
        int s2 = fp2[j];
        int s0 = fp1[s2];
        pos2[3*j+0] = pos0[3*s0+0];
        pos2[3*j+1] = pos0[3*s0+1];
        pos2[3*j+2] = pos0[3*s0+2];
        inv2[s2] = j;
    }
}

// one launch: histogram all 3 levels into g_cursor (pre-zeroed)
__global__ void hist3_k(const int* __restrict__ d0, const int* __restrict__ d1,
                        const int* __restrict__ d2, int* __restrict__ cur){
    int e = blockIdx.x*blockDim.x + threadIdx.x;
    if (e < E0)            atomicAdd(&cur[d0[e]], 1);
    else if (e < E0+E1)    atomicAdd(&cur[RPO1 + d1[e-E0]], 1);
    else if (e < E0+E1+E2) atomicAdd(&cur[RPO2 + d2[e-E0-E1]], 1);
}

// one launch, 3 blocks: block b scans level b (in-graph cost is small; ncu's
// large number for this kernel is an idle-clock/cold-cache profiling artifact)
__global__ void __launch_bounds__(1024) scan3_k(int* __restrict__ cursor, int* __restrict__ rowptr){
    int b = blockIdx.x;
    int n   = (b==0) ? N0 : (b==1) ? N1 : N2;
    int off = (b==0) ? 0  : (b==1) ? RPO1 : RPO2;
    int* cnt = cursor + off;
    int* rp  = rowptr + off;
    int t = threadIdx.x;
    int lane = t & 31, wid = t >> 5;
    int base = t*32;
    bool active = base < n;
    int s = 0;
    if (active){
        int vv[32];
        #pragma unroll
        for (int u = 0; u < 32; u++) vv[u] = cnt[base+u];
        #pragma unroll
        for (int u = 0; u < 32; u++) s += vv[u];
    }
    int inc = s;
    #pragma unroll
    for (int o = 1; o < 32; o <<= 1){
        int x = __shfl_up_sync(0xffffffffu, inc, o);
        if (lane >= o) inc += x;
    }
    __shared__ int wsum[32];
    if (lane == 31) wsum[wid] = inc;
    __syncthreads();
    if (wid == 0){
        int ws = wsum[lane];
        #pragma unroll
        for (int o = 1; o < 32; o <<= 1){
            int x = __shfl_up_sync(0xffffffffu, ws, o);
            if (lane >= o) ws += x;
        }
        wsum[lane] = ws;
    }
    __syncthreads();
    int excl = inc - s + ((wid > 0) ? wsum[wid-1] : 0);
    if (active){
        int vv[32];
        #pragma unroll
        for (int u = 0; u < 32; u++) vv[u] = cnt[base+u];
        int run = excl;
        #pragma unroll
        for (int u = 0; u < 32; u++){
            rp[base+u]  = run;
            cnt[base+u] = run;
            run += vv[u];
        }
    }
    if (t == 0) rp[n] = wsum[31];
}

// one launch: build CSR (source ids + rel/r in CSR order) for all 3 levels
__global__ void build3_k(const int* __restrict__ s0, const int* __restrict__ d0,
                         const int* __restrict__ s1, const int* __restrict__ d1,
                         const int* __restrict__ s2, const int* __restrict__ d2,
                         const float* __restrict__ p0, const float* __restrict__ p1,
                         const float* __restrict__ p2,
                         int* __restrict__ cursor, int* __restrict__ csrc,
                         float4* __restrict__ crelr){
    int e = blockIdx.x*blockDim.x + threadIdx.x;
    const int* srcp; const int* dstp; const float* pos;
    int rpo, eo, le;
    if (e < E0){ srcp=s0; dstp=d0; pos=p0; rpo=0;    eo=0;     le=e; }
    else if (e < E0+E1){ srcp=s1; dstp=d1; pos=p1; rpo=RPO1; eo=E0;    le=e-E0; }
    else if (e < E0+E1+E2){ srcp=s2; dstp=d2; pos=p2; rpo=RPO2; eo=E0+E1; le=e-E0-E1; }
    else return;
    int d = dstp[le];
    int s = srcp[le];
    int slot = atomicAdd(&cursor[rpo + d], 1);
    float dx = pos[3*d+0] - pos[3*s+0];
    float dy = pos[3*d+1] - pos[3*s+1];
    float dz = pos[3*d+2] - pos[3*s+2];
    float r = sqrtf(dx*dx + dy*dy + dz*dz + 1e-12f);
    csrc[eo + slot] = s;
    crelr[eo + slot] = make_float4(dx, dy, dz, r);
}

// ---------------- q,k,v,skip projection (smem-staged coalesced stores) -------
// MODE 0: x = base
// MODE 1: x = base / (cnt[node] + eps)             (pooled mean)
// MODE 2: x = base + (inv[node]>=0 ? add[..] : 0)  (upsample scatter + residual)
// Grids are exact (rows % 128 == 0), so no tail guard.
template<int CIN, int COUT, int MODE>
__global__ void __launch_bounds__(128) qkvs_k(
                       const float* __restrict__ base,
                       const float* __restrict__ aux_f,
                       const int* __restrict__ inv,
                       const float* __restrict__ Wq, const float* __restrict__ Wk,
                       const float* __restrict__ Wv, const float* __restrict__ Ws,
                       float* __restrict__ q, float* __restrict__ k,
                       float* __restrict__ v, float* __restrict__ sk, int rows){
    __shared__ __align__(16) float sW[4][CIN*COUT];
    __shared__ float swz[4][32][33];    // [warp][row-in-warp][chan], padded
    {
        const float* Wsrc[4] = {Wq, Wk, Wv, Ws};
        #pragma unroll
        for (int m2 = 0; m2 < 4; m2++)
            for (int i = threadIdx.x; i < CIN*COUT; i += blockDim.x)
                sW[m2][i] = Wsrc[m2][i];
    }
    __syncthreads();
    int t = blockIdx.x*blockDim.x + threadIdx.x;
    int lane = threadIdx.x & 31, wid = threadIdx.x >> 5;
    float xr[CIN];
    #pragma unroll
    for (int c = 0; c < CIN; c++) xr[c] = base[t*CIN + c];
    if (MODE == 1){
        float invc = 1.f/(aux_f[t/3] + 1e-9f);
        #pragma unroll
        for (int c = 0; c < CIN; c++) xr[c] *= invc;
    } else if (MODE == 2){
        int node = t/3, vc = t - node*3;
        int j = inv[node];
        if (j >= 0){
            const float* ap = aux_f + (j*3 + vc)*CIN;
            #pragma unroll
            for (int c = 0; c < CIN; c++) xr[c] += ap[c];
        }
    }
    float* outs[4] = {q, k, v, sk};
    int warp_row_base = blockIdx.x*blockDim.x + wid*32;   // first global row of this warp
    #pragma unroll
    for (int m2 = 0; m2 < 4; m2++){
        if (COUT == 1){
            float acc = 0.f;
            #pragma unroll
            for (int c = 0; c < CIN; c++) acc = fmaf(xr[c], sW[m2][c], acc);
            outs[m2][t] = acc;   // scalar per thread -> already coalesced
        } else {
            unsigned long long acc[16];
            #pragma unroll
            for (int op = 0; op < 16; op++) acc[op] = 0ULL;
            #pragma unroll
            for (int c = 0; c < CIN; c++){
                unsigned long long xx = pk2(xr[c], xr[c]);
                const ulonglong2* wp2 =
                    reinterpret_cast<const ulonglong2*>(&sW[m2][c*COUT]);
                #pragma unroll
                for (int o2 = 0; o2 < 8; o2++){
                    ulonglong2 w2 = wp2[o2];
                    acc[2*o2]   = ffma2(w2.x, xx, acc[2*o2]);
                    acc[2*o2+1] = ffma2(w2.y, xx, acc[2*o2+1]);
                }
            }
            // stage to smem (conflict-free via 33-pad), then coalesced global write
            #pragma unroll
            for (int op = 0; op < 16; op++){
                float2 f = upk2(acc[op]);
                swz[wid][lane][2*op]   = f.x;
                swz[wid][lane][2*op+1] = f.y;
            }
            __syncwarp();
            float* ob = outs[m2] + warp_row_base*COUT;
            #pragma unroll
            for (int r = 0; r < 32; r++)
                ob[r*COUT + lane] = swz[wid][r][lane];   // 128B fully-coalesced STG
            __syncwarp();
        }
    }
}

// ---------------- warp-per-node attention aggregation + norm_bias ------------
// MLPF: fuse the final 3->40 ReLU MLP head (only for COUT==1 last layer)
template<int COUT, bool MLPF>
__global__ void agg_k(const float* __restrict__ q, const float* __restrict__ k,
                      const float* __restrict__ v, const float* __restrict__ sk,
                      const int* __restrict__ rowptr, const int* __restrict__ csrc,
                      const float4* __restrict__ crelr,
                      const float* __restrict__ w1, const float* __restrict__ w2,
                      const float* __restrict__ scale, const float* __restrict__ bias,
                      float inv_scale, float* __restrict__ xout, int N,
                      const float* __restrict__ Wmlp, float* __restrict__ yout){
    int gw = (blockIdx.x*blockDim.x + threadIdx.x) >> 5;
    int lane = threadIdx.x & 31;
    if (gw >= N) return;
    int n = gw;
    float q0 = 0.f, q1 = 0.f, q2 = 0.f;
    if (lane < COUT){
        const float* qp = q + n*3*COUT;
        q0 = qp[lane]*inv_scale; q1 = qp[COUT+lane]*inv_scale; q2 = qp[2*COUT+lane]*inv_scale;
    }
    float w1v = 0.f, w2v = 0.f;
    if (lane < 16){ w1v = w1[lane]; w2v = w2[lane]; }
    int beg = rowptr[n], end = rowptr[n+1];
    float m = -INFINITY, ssum = 0.f, a0 = 0.f, a1 = 0.f, a2 = 0.f;

    int idx = beg;
    int s = (idx < end) ? csrc[idx] : 0;
    float4 rr = (idx < end) ? crelr[idx] : make_float4(0.f,0.f,0.f,0.f);
    while (idx < end){
        float k0=0.f,k1=0.f,k2=0.f, vv0=0.f,vv1=0.f,vv2=0.f;
        if (lane < COUT){
            const float* kp = k + s*3*COUT;
            const float* vp = v + s*3*COUT;
            k0 = kp[lane]; k1 = kp[COUT+lane]; k2 = kp[2*COUT+lane];
            vv0 = vp[lane]; vv1 = vp[COUT+lane]; vv2 = vp[2*COUT+lane];
        }
        int idxn = idx + 1;
        int sn = 0; float4 rrn = rr;
        if (idxn < end){ sn = csrc[idxn]; rrn = crelr[idxn]; }

        float part = (q0*k0 + q1*k1 + q2*k2)
                   + ((lane < 16) ? fmaxf(rr.w*w1v, 0.f)*w2v : 0.f);
        #pragma unroll
        for (int off = 16; off; off >>= 1) part += __shfl_xor_sync(0xffffffffu, part, off);
        float logit = part;
        float wgt;
        if (logit > m){
            float f = __expf(m - logit);
            ssum = ssum*f + 1.f;
            a0 *= f; a1 *= f; a2 *= f;
            m = logit; wgt = 1.f;
        } else {
            wgt = __expf(logit - m);
            ssum += wgt;
        }
        a0 = fmaf(wgt, vv0 + rr.x, a0);
        a1 = fmaf(wgt, vv1 + rr.y, a1);
        a2 = fmaf(wgt, vv2 + rr.z, a2);
        s = sn; rr = rrn; idx = idxn;
    }
    float o0 = 0.f, o1 = 0.f, o2 = 0.f;
    if (lane < COUT){
        float inv = 1.f/(ssum + 1e-9f);
        const float* sp = sk + n*3*COUT;
        o0 = a0*inv + sp[lane];
        o1 = a1*inv + sp[COUT+lane];
        o2 = a2*inv + sp[2*COUT+lane];
        float nrm = sqrtf(o0*o0 + o1*o1 + o2*o2 + 1e-12f);
        float tt = fmaxf(scale[lane]*nrm + bias[lane], 0.f)/nrm;
        o0 *= tt; o1 *= tt; o2 *= tt;
        if (!MLPF){
            float* op = xout + n*3*COUT;
            op[lane]        = o0;
            op[COUT+lane]   = o1;
            op[2*COUT+lane] = o2;
        }
    }
    if (MLPF){
        // broadcast lane 0's 3-vector, all lanes compute the 40 ReLU outputs
        float b0 = __shfl_sync(0xffffffffu, o0, 0);
        float b1 = __shfl_sync(0xffffffffu, o1, 0);
        float b2 = __shfl_sync(0xffffffffu, o2, 0);
        #pragma unroll
        for (int o = 0; o < 2; o++){
            int oc = lane + o*32;
            if (oc < 40){
                float a = b0*Wmlp[oc] + b1*Wmlp[40+oc] + b2*Wmlp[80+oc];
                yout[n*40 + oc] = fmaxf(a, 0.f);
            }
        }
    }
}

// ---------------- pooling ----------------
__global__ void pool_k(const float* __restrict__ x, const int* __restrict__ cl,
                       float* __restrict__ out, float* __restrict__ cnt, int Nsrc){
    int i = blockIdx.x*blockDim.x + threadIdx.x;
    if (i >= Nsrc*96) return;
    int j = i/96, e = i - j*96;
    int c = cl[j];
    atomicAdd(&out[c*96 + e], x[i]);
    if (e == 0) atomicAdd(&cnt[c], 1.f);
}

// ---------------- host orchestration ----------------
struct Ptrs {
    float *bufA, *bufB, *x0s, *x1s, *q, *k, *v, *s, *pos1, *pos2, *pool;
    int *rowptr, *cursor, *csrc, *inv;
    float4 *crelr;
};

// mode: 0 plain, 1 pooled-mean (aux=cnt), 2 upsample (aux=add, inv)
static void run_layer(const Ptrs& P, const float* xin, float* xout, int lvl,
                      int cin, int cout, int mode,
                      const float* aux_f, const int* inv,
                      const float* Wq, const float* Wk, const float* Wv, const float* Ws,
                      const float* sc, const float* bi,
                      const float* w1, const float* w2,
                      const float* Wmlp = nullptr, float* yout = nullptr){
    int n   = (lvl == 0) ? N0 : (lvl == 1) ? N1 : N2;
    int rpo = (lvl == 0) ? 0  : (lvl == 1) ? RPO1 : RPO2;
    int eo  = (lvl == 0) ? 0  : (lvl == 1) ? E0 : (E0+E1);
    int rows = n*3;
    int gb = rows/128;
    if (cin == 1)
        qkvs_k<1,32,0><<<gb,128>>>(xin, nullptr, nullptr, Wq, Wk, Wv, Ws, P.q, P.k, P.v, P.s, rows);
    else if (cout == 1)
        qkvs_k<32,1,0><<<gb,128>>>(xin, nullptr, nullptr, Wq, Wk, Wv, Ws, P.q, P.k, P.v, P.s, rows);
    else if (mode == 0)
        qkvs_k<32,32,0><<<gb,128>>>(xin, nullptr, nullptr, Wq, Wk, Wv, Ws, P.q, P.k, P.v, P.s, rows);
    else if (mode == 1)
        qkvs_k<32,32,1><<<gb,128>>>(xin, aux_f, nullptr, Wq, Wk, Wv, Ws, P.q, P.k, P.v, P.s, rows);
    else
        qkvs_k<32,32,2><<<gb,128>>>(xin, aux_f, inv, Wq, Wk, Wv, Ws, P.q, P.k, P.v, P.s, rows);
    float invs = 1.f/sqrtf(3.f*(float)cout);
    if (cout == 32)
        agg_k<32,false><<<n/8, 256>>>(P.q, P.k, P.v, P.s, P.rowptr+rpo, P.csrc+eo, P.crelr+eo,
                                      w1, w2, sc, bi, invs, xout, n, nullptr, nullptr);
    else
        agg_k<1,true><<<n/8, 256>>>(P.q, P.k, P.v, P.s, P.rowptr+rpo, P.csrc+eo, P.crelr+eo,
                                    w1, w2, sc, bi, invs, nullptr, n, Wmlp, yout);
}

extern "C" void kernel_launch(void* const* d_in, const int* in_sizes, int n_in,
                              void* d_out, int out_size){
    const float* pos0   = (const float*)d_in[0];
    const float* v0     = (const float*)d_in[1];
    const float* WqF    = (const float*)d_in[2];
    const float* WkF    = (const float*)d_in[3];
    const float* WvF    = (const float*)d_in[4];
    const float* WsF    = (const float*)d_in[5];
    const float* WqM    = (const float*)d_in[6];
    const float* WkM    = (const float*)d_in[7];
    const float* WvM    = (const float*)d_in[8];
    const float* WsM    = (const float*)d_in[9];
    const float* WqL    = (const float*)d_in[10];
    const float* WkL    = (const float*)d_in[11];
    const float* WvL    = (const float*)d_in[12];
    const float* WsL    = (const float*)d_in[13];
    const float* wr1    = (const float*)d_in[14];
    const float* wr2    = (const float*)d_in[15];
    const float* sc_mid = (const float*)d_in[16];
    const float* bi_mid = (const float*)d_in[17];
    const float* sc_las = (const float*)d_in[18];
    const float* bi_las = (const float*)d_in[19];
    const float* Wmlp   = (const float*)d_in[20];
    const int* src0 = (const int*)d_in[21];
    const int* dst0 = (const int*)d_in[22];
    const int* src1 = (const int*)d_in[23];
    const int* dst1 = (const int*)d_in[24];
    const int* src2 = (const int*)d_in[25];
    const int* dst2 = (const int*)d_in[26];
    const int* fp1  = (const int*)d_in[27];
    const int* fp2  = (const int*)d_in[28];
    const int* cl1  = (const int*)d_in[29];
    const int* cl2  = (const int*)d_in[30];
    float* out = (float*)d_out;

    Ptrs P;
    cudaGetSymbolAddress((void**)&P.bufA, g_bufA);
    cudaGetSymbolAddress((void**)&P.bufB, g_bufB);
    cudaGetSymbolAddress((void**)&P.x0s,  g_x0);
    cudaGetSymbolAddress((void**)&P.x1s,  g_x1);
    cudaGetSymbolAddress((void**)&P.q,    g_q);
    cudaGetSymbolAddress((void**)&P.k,    g_k);
    cudaGetSymbolAddress((void**)&P.v,    g_v);
    cudaGetSymbolAddress((void**)&P.s,    g_s);
    cudaGetSymbolAddress((void**)&P.pos1, g_pos1);
    cudaGetSymbolAddress((void**)&P.pos2, g_pos2);
    cudaGetSymbolAddress((void**)&P.pool, g_pool);
    cudaGetSymbolAddress((void**)&P.rowptr, g_rowptr);
    cudaGetSymbolAddress((void**)&P.cursor, g_cursor);
    cudaGetSymbolAddress((void**)&P.csrc,   g_csrc);
    cudaGetSymbolAddress((void**)&P.inv,    g_inv);
    cudaGetSymbolAddress((void**)&P.crelr,  g_crelr);

    int* inv1 = P.inv;        // [N0]: level0 node -> level1 slot (or -1)
    int* inv2 = P.inv + N0;   // [N1]: level1 node -> level2 slot (or -1)

    // setup: inverse maps + downsampled positions (one kernel)
    cudaMemsetAsync(P.inv, 0xFF, (N0+N1)*sizeof(int), 0);
    setup_k<<<(N1+N2+255)/256, 256>>>(pos0, fp1, fp2, P.pos1, P.pos2, inv1, inv2);

    // CSR build for all 3 levels
    cudaMemsetAsync(P.cursor, 0, RPTOT*sizeof(int), 0);
    {
        int ET = E0+E1+E2;
        hist3_k<<<(ET+255)/256, 256>>>(dst0, dst1, dst2, P.cursor);
        scan3_k<<<3, 1024>>>(P.cursor, P.rowptr);
        build3_k<<<(ET+255)/256, 256>>>(src0, dst0, src1, dst1, src2, dst2,
                                        pos0, P.pos1, P.pos2,
                                        P.cursor, P.csrc, P.crelr);
    }

    const int MW = 1024; // 32*32 mid-weight stride

    // down block 0 (level 0)
    run_layer(P, v0,     P.bufA, 0, 1, 32, 0, nullptr, nullptr, WqF, WkF, WvF, WsF,
              sc_mid+0,  bi_mid+0,  wr1+0,  wr2+0);
    run_layer(P, P.bufA, P.x0s,  0, 32, 32, 0, nullptr, nullptr,
              WqM+0*MW, WkM+0*MW, WvM+0*MW, WsM+0*MW,
              sc_mid+32, bi_mid+32, wr1+16, wr2+16);

    // pool -> level 1  ([N1*96 sums][N1 counts], one memset; mean folded into qkvs)
    cudaMemsetAsync(P.pool, 0, (N1*96 + N1)*sizeof(float), 0);
    pool_k<<<(N0*96+255)/256, 256>>>(P.x0s, cl1, P.pool, P.pool + N1*96, N0);

    run_layer(P, P.pool, P.bufB, 1, 32, 32, 1, P.pool + N1*96, nullptr,
              WqM+1*MW, WkM+1*MW, WvM+1*MW, WsM+1*MW,
              sc_mid+2*32, bi_mid+2*32, wr1+2*16, wr2+2*16);
    run_layer(P, P.bufB, P.x1s,  1, 32, 32, 0, nullptr, nullptr,
              WqM+2*MW, WkM+2*MW, WvM+2*MW, WsM+2*MW,
              sc_mid+3*32, bi_mid+3*32, wr1+3*16, wr2+3*16);

    // pool -> level 2
    cudaMemsetAsync(P.pool, 0, (N2*96 + N2)*sizeof(float), 0);
    pool_k<<<(N1*96+255)/256, 256>>>(P.x1s, cl2, P.pool, P.pool + N2*96, N1);

    // bottleneck
    run_layer(P, P.pool, P.bufB, 2, 32, 32, 1, P.pool + N2*96, nullptr,
              WqM+3*MW, WkM+3*MW, WvM+3*MW, WsM+3*MW,
              sc_mid+4*32, bi_mid+4*32, wr1+4*16, wr2+4*16);
    run_layer(P, P.bufB, P.bufA, 2, 32, 32, 0, nullptr, nullptr,
              WqM+4*MW, WkM+4*MW, WvM+4*MW, WsM+4*MW,
              sc_mid+5*32, bi_mid+5*32, wr1+5*16, wr2+5*16);

    // up block 0 (level 1): input = x1s + scatter(bufA via inv2), fused in qkvs
    run_layer(P, P.x1s, P.bufB, 1, 32, 32, 2, P.bufA, inv2,
              WqM+5*MW, WkM+5*MW, WvM+5*MW, WsM+5*MW,
              sc_mid+6*32, bi_mid+6*32, wr1+6*16, wr2+6*16);
    run_layer(P, P.bufB, P.bufA, 1, 32, 32, 0, nullptr, nullptr,
              WqM+6*MW, WkM+6*MW, WvM+6*MW, WsM+6*MW,
              sc_mid+7*32, bi_mid+7*32, wr1+7*16, wr2+7*16);

    // up block 1 (level 0): input = x0s + scatter(bufA via inv1), fused in qkvs
    run_layer(P, P.x0s, P.bufB, 0, 32, 32, 2, P.bufA, inv1,
              WqM+7*MW, WkM+7*MW, WvM+7*MW, WsM+7*MW,
              sc_mid+8*32, bi_mid+8*32, wr1+8*16, wr2+8*16);
    // final layer: cout=1 + fused MLP head (writes d_out directly)
    run_layer(P, P.bufB, nullptr, 0, 32, 1, 0, nullptr, nullptr, WqL, WkL, WvL, WsL,
              sc_las, bi_las, wr1+9*16, wr2+9*16, Wmlp, out);
}